// round 9
// baseline (speedup 1.0000x reference)
#include <cuda_runtime.h>
#include <cuda_fp16.h>
#include <math.h>
#include <stdint.h>

#define Bn 32
#define Tn 1024
#define Dn 512
#define Gn 256
#define En 8
#define Vn 8192

#define BM 128
#define BN 256
#define BK 32
#define GTHREADS 128
#define NTHREADS 256

#define L2E 1.4426950408889634f
#define LN2 0.6931471805599453f

// smem strides (bytes), padded for conflict-free ldmatrix
#define A_STRIDE 80      // 32 f16 = 64B + 16B pad
#define B_STRIDE 528     // 256 f16 = 512B + 16B pad
#define A_BYTES (BM * A_STRIDE)          // 10240
#define B_BYTES (BK * B_STRIDE)          // 16896
#define STAGE_BYTES (A_BYTES + B_BYTES)  // 27136
#define NSTAGES 3
#define SMEM_BYTES (NSTAGES * STAGE_BYTES)  // 81408 per CTA, 2 CTAs/SM

// ---------------- scratch (no cudaMalloc allowed) ----------------
__device__ __half g_Xh[(size_t)Bn * Tn * Dn];   // [B,T,D]
__device__ __half g_Wh[(size_t)En * Dn * Vn];   // [E,D,V]
__device__ float g_sumexp[Bn * Tn];
__device__ float g_tgt[Bn * Tn];                // stores logit * log2(e)
__device__ int   g_assign[Bn];
__device__ float g_ce[Bn];

// ---------------- helpers ----------------
__device__ __forceinline__ uint32_t s2u(const void* p) {
    uint32_t a;
    asm("{ .reg .u64 t; cvta.to.shared.u64 t, %1; cvt.u32.u64 %0, t; }" : "=r"(a) : "l"(p));
    return a;
}
__device__ __forceinline__ void cp16(uint32_t dst, const void* src) {
    asm volatile("cp.async.cg.shared.global [%0], [%1], 16;" :: "r"(dst), "l"(src) : "memory");
}
__device__ __forceinline__ void cp_commit() { asm volatile("cp.async.commit_group;" ::: "memory"); }

__device__ __forceinline__ void ldsm_x4(uint32_t& r0, uint32_t& r1, uint32_t& r2, uint32_t& r3, uint32_t a) {
    asm volatile("ldmatrix.sync.aligned.m8n8.x4.shared.b16 {%0,%1,%2,%3}, [%4];"
                 : "=r"(r0), "=r"(r1), "=r"(r2), "=r"(r3) : "r"(a));
}
__device__ __forceinline__ void ldsm_x4t(uint32_t& r0, uint32_t& r1, uint32_t& r2, uint32_t& r3, uint32_t a) {
    asm volatile("ldmatrix.sync.aligned.m8n8.x4.trans.shared.b16 {%0,%1,%2,%3}, [%4];"
                 : "=r"(r0), "=r"(r1), "=r"(r2), "=r"(r3) : "r"(a));
}
__device__ __forceinline__ void mma_f16(uint32_t* d, const uint32_t* a, const uint32_t* b) {
    asm volatile("mma.sync.aligned.m16n8k16.row.col.f16.f16.f16.f16 "
                 "{%0,%1}, {%2,%3,%4,%5}, {%6,%7}, {%0,%1};"
                 : "+r"(d[0]), "+r"(d[1])
                 : "r"(a[0]), "r"(a[1]), "r"(a[2]), "r"(a[3]), "r"(b[0]), "r"(b[1]));
}
__device__ __forceinline__ __half2 h2ex2(__half2 x) {
    __half2 r;
    asm("ex2.approx.f16x2 %0, %1;" : "=r"(*(uint32_t*)&r) : "r"(*(uint32_t*)&x));
    return r;
}

// ---------------- conversion kernels (fp32 -> f16) ----------------
__global__ void convert_x_kernel(const float4* __restrict__ X) {
    size_t i = (size_t)blockIdx.x * blockDim.x + threadIdx.x;
    float4 v = X[i];
    __half2* o = (__half2*)g_Xh;
    o[2 * i + 0] = __floats2half2_rn(v.x, v.y);
    o[2 * i + 1] = __floats2half2_rn(v.z, v.w);
}
__global__ void convert_w_kernel(const float4* __restrict__ W) {
    size_t i = (size_t)blockIdx.x * blockDim.x + threadIdx.x;
    float4 v = W[i];
    __half2* o = (__half2*)g_Wh;
    o[2 * i + 0] = __floats2half2_rn(v.x, v.y);
    o[2 * i + 1] = __floats2half2_rn(v.z, v.w);
}

// ---------------- router ----------------
__global__ void router_kernel(const float* __restrict__ gate,
                              const float* __restrict__ Wg,
                              const float* __restrict__ bg,
                              float* __restrict__ out, int out_size)
{
    int tid = threadIdx.x;
    for (int i = tid; i < out_size; i += NTHREADS) out[i] = 0.0f;
    for (int i = tid; i < Bn * Tn; i += NTHREADS) g_sumexp[i] = 0.0f;

    __shared__ float logits[Bn][En];
    int i = tid / En, j = tid % En;
    float acc = bg[j];
    const float* grow = gate + i * Gn;
    #pragma unroll 4
    for (int g = 0; g < Gn; g++) acc += grow[g] * Wg[g * En + j];
    logits[i][j] = acc;
    __syncthreads();

    if (tid < Bn) {
        float mx = logits[tid][0];
        int am = 0;
        #pragma unroll
        for (int e = 1; e < En; e++) {
            float v = logits[tid][e];
            if (v > mx) { mx = v; am = e; }
        }
        float ex[En], s = 0.0f;
        #pragma unroll
        for (int e = 0; e < En; e++) { ex[e] = expf(logits[tid][e] - mx); s += ex[e]; }
        float inv = 1.0f / s;
        #pragma unroll
        for (int e = 0; e < En; e++) out[1 + Bn + tid * En + e] = ex[e] * inv;
        out[1 + tid] = (float)am;
        g_assign[tid] = am;
    }
}

// ---------------- fused HMMA GEMM + CE epilogue ----------------
// grid (V/BN=32, T/BM=8, B=32), 128 threads, 4 warps: warp grid 2(M) x 2(N),
// warp tile 64x128 with f16 accumulators, 2 CTAs/SM.
__device__ __forceinline__ void load_stage(uint32_t sA, uint32_t sB,
                                           const __half* Ag,
                                           const __half* Bg,
                                           int k0, int tid)
{
    // A: 128 rows x 32 f16 (64B) = 512 x 16B segs; 4 per thread
    #pragma unroll
    for (int i = 0; i < 4; i++) {
        int s = tid + i * GTHREADS;
        int row = s >> 2, j = s & 3;
        cp16(sA + (uint32_t)(row * A_STRIDE + j * 16),
             Ag + (size_t)row * Dn + k0 + j * 8);
    }
    // B: 32 k-rows x 256 f16 (512B) = 1024 x 16B segs; 8 per thread
    #pragma unroll
    for (int i = 0; i < 8; i++) {
        int s = tid + i * GTHREADS;
        int kr = s >> 5, j = s & 31;
        cp16(sB + (uint32_t)(kr * B_STRIDE + j * 16),
             Bg + (size_t)(k0 + kr) * Vn + j * 8);
    }
}

__global__ void __launch_bounds__(GTHREADS, 2)
gemm_ce_kernel(const float* __restrict__ be, const int* __restrict__ tgt32)
{
    extern __shared__ char smem[];
    const uint32_t sbase = s2u(smem);
    const int tid  = threadIdx.x;
    const int wid  = tid >> 5;
    const int lane = tid & 31;
    const int wm   = wid >> 1;    // 0..1 (64 rows)
    const int wn   = wid & 1;     // 0..1 (128 cols)

    const int vt = blockIdx.x, tt = blockIdx.y, b = blockIdx.z;
    const int e  = g_assign[b];
    const int v0 = vt * BN;
    const int t0 = tt * BM;

    const __half* Ag = g_Xh + ((size_t)b * Tn + t0) * Dn;
    const __half* Bg = g_Wh + (size_t)e * Dn * Vn + v0;

    uint32_t acc[4][16][2];
    #pragma unroll
    for (int mt = 0; mt < 4; mt++)
        #pragma unroll
        for (int nt = 0; nt < 16; nt++) { acc[mt][nt][0] = 0u; acc[mt][nt][1] = 0u; }

    const uint32_t a_lane_off = (uint32_t)((lane & 15) * A_STRIDE + (lane >> 4) * 16)
                              + (uint32_t)(wm * 64 * A_STRIDE);
    const uint32_t b_lane_off = (uint32_t)((lane & 15) * B_STRIDE
                              + (wn * 128 + (lane >> 4) * 8) * 2);

    uint32_t sA[NSTAGES], sB[NSTAGES];
    #pragma unroll
    for (int s = 0; s < NSTAGES; s++) {
        sA[s] = sbase + s * STAGE_BYTES;
        sB[s] = sbase + s * STAGE_BYTES + A_BYTES;
    }

    load_stage(sA[0], sB[0], Ag, Bg, 0, tid);  cp_commit();
    load_stage(sA[1], sB[1], Ag, Bg, BK, tid); cp_commit();

    const int NCHUNK = Dn / BK;   // 16
    int stage = 0;
    #pragma unroll 1
    for (int c = 0; c < NCHUNK; c++) {
        if (c < NCHUNK - 1) asm volatile("cp.async.wait_group 1;" ::: "memory");
        else                asm volatile("cp.async.wait_group 0;" ::: "memory");
        __syncthreads();

        if (c + 2 < NCHUNK) {
            int ws = stage + 2; if (ws >= NSTAGES) ws -= NSTAGES;
            load_stage(sA[ws], sB[ws], Ag, Bg, (c + 2) * BK, tid);
            cp_commit();
        }

        const uint32_t aBase = sA[stage] + a_lane_off;
        const uint32_t bBase = sB[stage] + b_lane_off;

        #pragma unroll
        for (int kt = 0; kt < 2; kt++) {
            uint32_t af[4][4], bf[32];
            #pragma unroll
            for (int mt = 0; mt < 4; mt++)
                ldsm_x4(af[mt][0], af[mt][1], af[mt][2], af[mt][3],
                        aBase + (uint32_t)(mt * 16 * A_STRIDE + kt * 32));
            // eight x4.trans cover nt pairs {0,1}..{14,15}
            #pragma unroll
            for (int g = 0; g < 8; g++)
                ldsm_x4t(bf[g * 4 + 0], bf[g * 4 + 1], bf[g * 4 + 2], bf[g * 4 + 3],
                         bBase + (uint32_t)(kt * 16 * B_STRIDE + g * 32));
            #pragma unroll
            for (int mt = 0; mt < 4; mt++)
                #pragma unroll
                for (int nt = 0; nt < 16; nt++)
                    mma_f16(acc[mt][nt], af[mt], &bf[nt * 2]);
        }
        if (++stage == NSTAGES) stage = 0;
    }

    // ---- epilogue: t = logit*log2e in half2; exp via ex2.f16x2 ----
    const int c0 = (lane & 3) * 2;
    const int r0 = lane >> 2;
    const int vbase = v0 + wn * 128 + c0;
    const float* bias_base = be + (size_t)e * Vn + vbase;

    const __half2 l2e = __float2half2_rn(L2E);

    #pragma unroll
    for (int mt = 0; mt < 4; mt++) {
        const int row0 = t0 + wm * 64 + mt * 16 + r0;
        const int row1 = row0 + 8;
        const int d0 = tgt32[2 * (b * Tn + row0)] - vbase;   // int64 targets, low word
        const int d1 = tgt32[2 * (b * Tn + row1)] - vbase;
        float s0 = 0.0f, s1 = 0.0f;
        #pragma unroll
        for (int nt = 0; nt < 16; nt++) {
            __half2 bsc = __floats2half2_rn(bias_base[nt * 8] * L2E,
                                            bias_base[nt * 8 + 1] * L2E);
            __half2 a0 = *(__half2*)&acc[mt][nt][0];
            __half2 a1 = *(__half2*)&acc[mt][nt][1];
            __half2 t0h = __hfma2(a0, l2e, bsc);
            __half2 t1h = __hfma2(a1, l2e, bsc);
            float2 e0 = __half22float2(h2ex2(t0h));
            float2 e1 = __half22float2(h2ex2(t1h));
            s0 += e0.x + e0.y;
            s1 += e1.x + e1.y;
            if (d0 == nt * 8)     g_tgt[(size_t)b * Tn + row0] = __low2float(t0h);
            if (d0 == nt * 8 + 1) g_tgt[(size_t)b * Tn + row0] = __high2float(t0h);
            if (d1 == nt * 8)     g_tgt[(size_t)b * Tn + row1] = __low2float(t1h);
            if (d1 == nt * 8 + 1) g_tgt[(size_t)b * Tn + row1] = __high2float(t1h);
        }
        s0 += __shfl_xor_sync(0xffffffffu, s0, 1);
        s0 += __shfl_xor_sync(0xffffffffu, s0, 2);
        s1 += __shfl_xor_sync(0xffffffffu, s1, 1);
        s1 += __shfl_xor_sync(0xffffffffu, s1, 2);
        if ((lane & 3) == 0) {
            atomicAdd(&g_sumexp[(size_t)b * Tn + row0], s0);
            atomicAdd(&g_sumexp[(size_t)b * Tn + row1], s1);
        }
    }
}

// ---------------- CE reductions ----------------
__global__ void ce_reduce_kernel()
{
    const int b = blockIdx.x;
    const int tid = threadIdx.x;
    float s = 0.0f;
    for (int t = tid; t < Tn; t += NTHREADS) {
        const int idx = b * Tn + t;
        s += logf(g_sumexp[idx]) - g_tgt[idx] * LN2;   // g_tgt holds logit*log2e
    }
    __shared__ float red[NTHREADS];
    red[tid] = s;
    __syncthreads();
    for (int off = NTHREADS / 2; off > 0; off >>= 1) {
        if (tid < off) red[tid] += red[tid + off];
        __syncthreads();
    }
    if (tid == 0) g_ce[b] = red[0] / (float)Tn;
}

__global__ void final_kernel(float* __restrict__ out)
{
    if (threadIdx.x == 0) {
        float sums[En], cnt[En];
        #pragma unroll
        for (int e = 0; e < En; e++) { sums[e] = 0.0f; cnt[e] = 0.0f; }
        for (int b = 0; b < Bn; b++) {
            sums[g_assign[b]] += g_ce[b];
            cnt[g_assign[b]]  += 1.0f;
        }
        float tot = 0.0f;
        #pragma unroll
        for (int e = 0; e < En; e++)
            if (cnt[e] > 0.0f) tot += sums[e] / cnt[e];
        out[0] = tot;
    }
}

// ---------------- launcher ----------------
extern "C" void kernel_launch(void* const* d_in, const int* in_sizes, int n_in,
                              void* d_out, int out_size)
{
    const float* gate = (const float*)d_in[0];
    const float* X    = (const float*)d_in[1];
    const float* Wg   = (const float*)d_in[2];
    const float* bg   = (const float*)d_in[3];
    const float* We   = (const float*)d_in[4];
    const float* be   = (const float*)d_in[5];
    const int*   tgt  = (const int*)d_in[6];
    float* out = (float*)d_out;

    cudaFuncSetAttribute(gemm_ce_kernel, cudaFuncAttributeMaxDynamicSharedMemorySize, SMEM_BYTES);

    convert_x_kernel<<<((size_t)Bn * Tn * Dn / 4) / 256, 256>>>((const float4*)X);
    convert_w_kernel<<<((size_t)En * Dn * Vn / 4) / 256, 256>>>((const float4*)We);

    router_kernel<<<1, NTHREADS>>>(gate, Wg, bg, out, out_size);

    dim3 grid(Vn / BN, Tn / BM, Bn);
    gemm_ce_kernel<<<grid, GTHREADS, SMEM_BYTES>>>(be, tgt);

    ce_reduce_kernel<<<Bn, NTHREADS>>>();
    final_kernel<<<1, 32>>>(out);
}

// round 10
// speedup vs baseline: 1.3203x; 1.3203x over previous
#include <cuda_runtime.h>
#include <cuda_fp16.h>
#include <math.h>
#include <stdint.h>

#define Bn 32
#define Tn 1024
#define Dn 512
#define Gn 256
#define En 8
#define Vn 8192

#define BM 128
#define BN 128
#define BK 32
#define GTHREADS 128
#define NTHREADS 256

#define L2E 1.4426950408889634f
#define LN2 0.6931471805599453f

// smem strides (bytes), padded for conflict-free ldmatrix
#define A_STRIDE 80      // 32 f16 = 64B + 16B pad
#define B_STRIDE 272     // 128 f16 = 256B + 16B pad
#define A_BYTES (BM * A_STRIDE)          // 10240
#define B_BYTES (BK * B_STRIDE)          // 8704
#define STAGE_BYTES (A_BYTES + B_BYTES)  // 18944
#define NSTAGES 3
#define SM_MBAR (NSTAGES * STAGE_BYTES)  // 56832
#define SMEM_BYTES (SM_MBAR + 64)        // 56896 per CTA, 4 CTAs/SM

// ---------------- scratch (no cudaMalloc allowed) ----------------
__device__ __half g_Xh[(size_t)Bn * Tn * Dn];   // [B,T,D]
__device__ __half g_Wh[(size_t)En * Dn * Vn];   // [E,D,V]
__device__ float g_sumexp[Bn * Tn];
__device__ float g_tgt[Bn * Tn];                // stores logit * log2(e)
__device__ int   g_assign[Bn];
__device__ float g_ce[Bn];

// ---------------- helpers ----------------
__device__ __forceinline__ uint32_t s2u(const void* p) {
    uint32_t a;
    asm("{ .reg .u64 t; cvta.to.shared.u64 t, %1; cvt.u32.u64 %0, t; }" : "=r"(a) : "l"(p));
    return a;
}
__device__ __forceinline__ void cp16(uint32_t dst, const void* src) {
    asm volatile("cp.async.cg.shared.global [%0], [%1], 16;" :: "r"(dst), "l"(src) : "memory");
}
__device__ __forceinline__ void mwait(uint32_t addr, uint32_t phase) {
    asm volatile(
        "{\n\t.reg .pred P;\n\t"
        "WL_%=:\n\t"
        "mbarrier.try_wait.parity.acquire.cta.shared::cta.b64 P, [%0], %1, 0x989680;\n\t"
        "@P bra WD_%=;\n\t"
        "bra WL_%=;\n\t"
        "WD_%=:\n\t}"
        :: "r"(addr), "r"(phase) : "memory");
}
__device__ __forceinline__ void mbar_init(uint32_t a, uint32_t cnt) {
    asm volatile("mbarrier.init.shared::cta.b64 [%0], %1;" :: "r"(a), "r"(cnt) : "memory");
}
__device__ __forceinline__ void mbar_arrive(uint32_t a) {
    asm volatile("mbarrier.arrive.shared::cta.b64 _, [%0];" :: "r"(a) : "memory");
}
__device__ __forceinline__ void cpasync_arrive(uint32_t a) {
    asm volatile("cp.async.mbarrier.arrive.noinc.shared::cta.b64 [%0];" :: "r"(a) : "memory");
}

__device__ __forceinline__ void ldsm_x4(uint32_t& r0, uint32_t& r1, uint32_t& r2, uint32_t& r3, uint32_t a) {
    asm volatile("ldmatrix.sync.aligned.m8n8.x4.shared.b16 {%0,%1,%2,%3}, [%4];"
                 : "=r"(r0), "=r"(r1), "=r"(r2), "=r"(r3) : "r"(a));
}
__device__ __forceinline__ void ldsm_x4t(uint32_t& r0, uint32_t& r1, uint32_t& r2, uint32_t& r3, uint32_t a) {
    asm volatile("ldmatrix.sync.aligned.m8n8.x4.trans.shared.b16 {%0,%1,%2,%3}, [%4];"
                 : "=r"(r0), "=r"(r1), "=r"(r2), "=r"(r3) : "r"(a));
}
__device__ __forceinline__ void mma_f16(uint32_t* d, const uint32_t* a, const uint32_t* b) {
    asm volatile("mma.sync.aligned.m16n8k16.row.col.f16.f16.f16.f16 "
                 "{%0,%1}, {%2,%3,%4,%5}, {%6,%7}, {%0,%1};"
                 : "+r"(d[0]), "+r"(d[1])
                 : "r"(a[0]), "r"(a[1]), "r"(a[2]), "r"(a[3]), "r"(b[0]), "r"(b[1]));
}
__device__ __forceinline__ __half2 h2ex2(__half2 x) {
    __half2 r;
    asm("ex2.approx.f16x2 %0, %1;" : "=r"(*(uint32_t*)&r) : "r"(*(uint32_t*)&x));
    return r;
}

// ---------------- conversion kernels (fp32 -> f16) ----------------
__global__ void convert_x_kernel(const float4* __restrict__ X) {
    size_t i = (size_t)blockIdx.x * blockDim.x + threadIdx.x;
    float4 v = X[i];
    __half2* o = (__half2*)g_Xh;
    o[2 * i + 0] = __floats2half2_rn(v.x, v.y);
    o[2 * i + 1] = __floats2half2_rn(v.z, v.w);
}
__global__ void convert_w_kernel(const float4* __restrict__ W) {
    size_t i = (size_t)blockIdx.x * blockDim.x + threadIdx.x;
    float4 v = W[i];
    __half2* o = (__half2*)g_Wh;
    o[2 * i + 0] = __floats2half2_rn(v.x, v.y);
    o[2 * i + 1] = __floats2half2_rn(v.z, v.w);
}

// ---------------- router ----------------
__global__ void router_kernel(const float* __restrict__ gate,
                              const float* __restrict__ Wg,
                              const float* __restrict__ bg,
                              float* __restrict__ out, int out_size)
{
    int tid = threadIdx.x;
    for (int i = tid; i < out_size; i += NTHREADS) out[i] = 0.0f;
    for (int i = tid; i < Bn * Tn; i += NTHREADS) g_sumexp[i] = 0.0f;

    __shared__ float logits[Bn][En];
    int i = tid / En, j = tid % En;
    float acc = bg[j];
    const float* grow = gate + i * Gn;
    #pragma unroll 4
    for (int g = 0; g < Gn; g++) acc += grow[g] * Wg[g * En + j];
    logits[i][j] = acc;
    __syncthreads();

    if (tid < Bn) {
        float mx = logits[tid][0];
        int am = 0;
        #pragma unroll
        for (int e = 1; e < En; e++) {
            float v = logits[tid][e];
            if (v > mx) { mx = v; am = e; }
        }
        float ex[En], s = 0.0f;
        #pragma unroll
        for (int e = 0; e < En; e++) { ex[e] = expf(logits[tid][e] - mx); s += ex[e]; }
        float inv = 1.0f / s;
        #pragma unroll
        for (int e = 0; e < En; e++) out[1 + Bn + tid * En + e] = ex[e] * inv;
        out[1 + tid] = (float)am;
        g_assign[tid] = am;
    }
}

// ---------------- fused HMMA GEMM + CE epilogue ----------------
// grid (V/BN=64, T/BM=8, B=32), 128 threads, 4 warps: warp grid 2(M) x 2(N),
// warp tile 64x64 f16 acc, 4 CTAs/SM. mbarrier ring pipeline, no __syncthreads
// in the mainloop.
__device__ __forceinline__ void load_stage(uint32_t sA, uint32_t sB,
                                           const __half* Ag,
                                           const __half* Bg,
                                           int k0, int tid)
{
    #pragma unroll
    for (int i = 0; i < 4; i++) {
        int s = tid + i * GTHREADS;
        int row = s >> 2, j = s & 3;
        cp16(sA + (uint32_t)(row * A_STRIDE + j * 16),
             Ag + (size_t)row * Dn + k0 + j * 8);
    }
    #pragma unroll
    for (int i = 0; i < 4; i++) {
        int s = tid + i * GTHREADS;
        int kr = s >> 4, j = s & 15;
        cp16(sB + (uint32_t)(kr * B_STRIDE + j * 16),
             Bg + (size_t)(k0 + kr) * Vn + j * 8);
    }
}

__global__ void __launch_bounds__(GTHREADS, 4)
gemm_ce_kernel(const float* __restrict__ be, const int* __restrict__ tgt32)
{
    extern __shared__ char smem[];
    const uint32_t sbase = s2u(smem);
    const uint32_t mbase = sbase + SM_MBAR;   // full[s]=+s*16, free[s]=+s*16+8
    const int tid  = threadIdx.x;
    const int wid  = tid >> 5;
    const int lane = tid & 31;
    const int wm   = wid >> 1;    // 0..1 (64 rows)
    const int wn   = wid & 1;     // 0..1 (64 cols)

    const int vt = blockIdx.x, tt = blockIdx.y, b = blockIdx.z;
    const int e  = g_assign[b];
    const int v0 = vt * BN;
    const int t0 = tt * BM;

    const __half* Ag = g_Xh + ((size_t)b * Tn + t0) * Dn;
    const __half* Bg = g_Wh + (size_t)e * Dn * Vn + v0;

    if (tid == 0) {
        #pragma unroll
        for (int s = 0; s < NSTAGES; s++) {
            mbar_init(mbase + s * 16,     128);  // full: per-thread cp.async arrive
            mbar_init(mbase + s * 16 + 8, 4);    // free: one arrive per warp
        }
    }
    __syncthreads();   // the only CTA barrier

    uint32_t acc[4][8][2];
    #pragma unroll
    for (int mt = 0; mt < 4; mt++)
        #pragma unroll
        for (int nt = 0; nt < 8; nt++) { acc[mt][nt][0] = 0u; acc[mt][nt][1] = 0u; }

    const uint32_t a_lane_off = (uint32_t)((lane & 15) * A_STRIDE + (lane >> 4) * 16)
                              + (uint32_t)(wm * 64 * A_STRIDE);
    const uint32_t b_lane_off = (uint32_t)((lane & 15) * B_STRIDE
                              + (wn * 64 + (lane >> 4) * 8) * 2);

    uint32_t prod_ph = 7u;   // parity bit per stage, producers start at 1
    uint32_t cons_ph = 0u;   // consumers start at 0

    // prologue: produce chunks 0,1 into stages 0,1 (free-waits pass immediately)
    #pragma unroll
    for (int k = 0; k < 2; k++) {
        mwait(mbase + k * 16 + 8, (prod_ph >> k) & 1u);
        prod_ph ^= (1u << k);
        load_stage(sbase + k * STAGE_BYTES, sbase + k * STAGE_BYTES + A_BYTES,
                   Ag, Bg, k * BK, tid);
        cpasync_arrive(mbase + k * 16);
    }

    const int NCHUNK = Dn / BK;   // 16
    int ps = 2, cs = 0;
    #pragma unroll 1
    for (int c = 0; c < NCHUNK; c++) {
        // produce chunk c+2 into stage ps (ring-safe: that stage was consumed at c-1)
        if (c + 2 < NCHUNK) {
            mwait(mbase + ps * 16 + 8, (prod_ph >> ps) & 1u);
            prod_ph ^= (1u << ps);
            load_stage(sbase + ps * STAGE_BYTES, sbase + ps * STAGE_BYTES + A_BYTES,
                       Ag, Bg, (c + 2) * BK, tid);
            cpasync_arrive(mbase + ps * 16);
            if (++ps == NSTAGES) ps = 0;
        }

        // consume chunk c from stage cs
        mwait(mbase + cs * 16, (cons_ph >> cs) & 1u);
        cons_ph ^= (1u << cs);

        const uint32_t aBase = sbase + cs * STAGE_BYTES + a_lane_off;
        const uint32_t bBase = sbase + cs * STAGE_BYTES + A_BYTES + b_lane_off;

        #pragma unroll
        for (int kt = 0; kt < 2; kt++) {
            uint32_t af[4][4], bf[16];
            #pragma unroll
            for (int mt = 0; mt < 4; mt++)
                ldsm_x4(af[mt][0], af[mt][1], af[mt][2], af[mt][3],
                        aBase + (uint32_t)(mt * 16 * A_STRIDE + kt * 32));
            #pragma unroll
            for (int g = 0; g < 4; g++)
                ldsm_x4t(bf[g * 4 + 0], bf[g * 4 + 1], bf[g * 4 + 2], bf[g * 4 + 3],
                         bBase + (uint32_t)(kt * 16 * B_STRIDE + g * 32));
            #pragma unroll
            for (int mt = 0; mt < 4; mt++)
                #pragma unroll
                for (int nt = 0; nt < 8; nt++)
                    mma_f16(acc[mt][nt], af[mt], &bf[nt * 2]);
        }

        __syncwarp();
        if (lane == 0) mbar_arrive(mbase + cs * 16 + 8);   // stage free
        if (++cs == NSTAGES) cs = 0;
    }

    // ---- epilogue: t = logit*log2e in half2; exp via ex2.f16x2 ----
    const int c0 = (lane & 3) * 2;
    const int r0 = lane >> 2;
    const int vbase = v0 + wn * 64 + c0;
    const float* bias_base = be + (size_t)e * Vn + vbase;

    const __half2 l2e = __float2half2_rn(L2E);
    __half2 bsc[8];
    #pragma unroll
    for (int nt = 0; nt < 8; nt++)
        bsc[nt] = __floats2half2_rn(bias_base[nt * 8] * L2E, bias_base[nt * 8 + 1] * L2E);

    #pragma unroll
    for (int mt = 0; mt < 4; mt++) {
        const int row0 = t0 + wm * 64 + mt * 16 + r0;
        const int row1 = row0 + 8;
        const int d0 = tgt32[2 * (b * Tn + row0)] - vbase;   // int64 targets, low word
        const int d1 = tgt32[2 * (b * Tn + row1)] - vbase;
        float s0 = 0.0f, s1 = 0.0f;
        #pragma unroll
        for (int nt = 0; nt < 8; nt++) {
            __half2 a0 = *(__half2*)&acc[mt][nt][0];
            __half2 a1 = *(__half2*)&acc[mt][nt][1];
            __half2 t0h = __hfma2(a0, l2e, bsc[nt]);
            __half2 t1h = __hfma2(a1, l2e, bsc[nt]);
            float2 e0 = __half22float2(h2ex2(t0h));
            float2 e1 = __half22float2(h2ex2(t1h));
            s0 += e0.x + e0.y;
            s1 += e1.x + e1.y;
            if (d0 == nt * 8)     g_tgt[(size_t)b * Tn + row0] = __low2float(t0h);
            if (d0 == nt * 8 + 1) g_tgt[(size_t)b * Tn + row0] = __high2float(t0h);
            if (d1 == nt * 8)     g_tgt[(size_t)b * Tn + row1] = __low2float(t1h);
            if (d1 == nt * 8 + 1) g_tgt[(size_t)b * Tn + row1] = __high2float(t1h);
        }
        s0 += __shfl_xor_sync(0xffffffffu, s0, 1);
        s0 += __shfl_xor_sync(0xffffffffu, s0, 2);
        s1 += __shfl_xor_sync(0xffffffffu, s1, 1);
        s1 += __shfl_xor_sync(0xffffffffu, s1, 2);
        if ((lane & 3) == 0) {
            atomicAdd(&g_sumexp[(size_t)b * Tn + row0], s0);
            atomicAdd(&g_sumexp[(size_t)b * Tn + row1], s1);
        }
    }
}

// ---------------- CE reductions ----------------
__global__ void ce_reduce_kernel()
{
    const int b = blockIdx.x;
    const int tid = threadIdx.x;
    float s = 0.0f;
    for (int t = tid; t < Tn; t += NTHREADS) {
        const int idx = b * Tn + t;
        s += logf(g_sumexp[idx]) - g_tgt[idx] * LN2;   // g_tgt holds logit*log2e
    }
    __shared__ float red[NTHREADS];
    red[tid] = s;
    __syncthreads();
    for (int off = NTHREADS / 2; off > 0; off >>= 1) {
        if (tid < off) red[tid] += red[tid + off];
        __syncthreads();
    }
    if (tid == 0) g_ce[b] = red[0] / (float)Tn;
}

__global__ void final_kernel(float* __restrict__ out)
{
    if (threadIdx.x == 0) {
        float sums[En], cnt[En];
        #pragma unroll
        for (int e = 0; e < En; e++) { sums[e] = 0.0f; cnt[e] = 0.0f; }
        for (int b = 0; b < Bn; b++) {
            sums[g_assign[b]] += g_ce[b];
            cnt[g_assign[b]]  += 1.0f;
        }
        float tot = 0.0f;
        #pragma unroll
        for (int e = 0; e < En; e++)
            if (cnt[e] > 0.0f) tot += sums[e] / cnt[e];
        out[0] = tot;
    }
}

// ---------------- launcher ----------------
extern "C" void kernel_launch(void* const* d_in, const int* in_sizes, int n_in,
                              void* d_out, int out_size)
{
    const float* gate = (const float*)d_in[0];
    const float* X    = (const float*)d_in[1];
    const float* Wg   = (const float*)d_in[2];
    const float* bg   = (const float*)d_in[3];
    const float* We   = (const float*)d_in[4];
    const float* be   = (const float*)d_in[5];
    const int*   tgt  = (const int*)d_in[6];
    float* out = (float*)d_out;

    cudaFuncSetAttribute(gemm_ce_kernel, cudaFuncAttributeMaxDynamicSharedMemorySize, SMEM_BYTES);

    convert_x_kernel<<<((size_t)Bn * Tn * Dn / 4) / 256, 256>>>((const float4*)X);
    convert_w_kernel<<<((size_t)En * Dn * Vn / 4) / 256, 256>>>((const float4*)We);

    router_kernel<<<1, NTHREADS>>>(gate, Wg, bg, out, out_size);

    dim3 grid(Vn / BN, Tn / BM, Bn);
    gemm_ce_kernel<<<grid, GTHREADS, SMEM_BYTES>>>(be, tgt);

    ce_reduce_kernel<<<Bn, NTHREADS>>>();
    final_kernel<<<1, 32>>>(out);
}